// round 1
// baseline (speedup 1.0000x reference)
#include <cuda_runtime.h>
#include <math.h>

#define N_NODES 50000
#define N_EDGES 800000
#define N_TOT   (N_EDGES + N_NODES)   // edges + self loops
#define HID     128
#define N_GRAPHS 32
#define LN_EPS  1e-5f

// ---------------- scratch (device globals; no allocation allowed) ------------
__device__ float g_hcur [N_NODES * HID];
__device__ float g_hfeat[N_NODES * HID];
__device__ float g_agg  [N_NODES * HID];
__device__ float g_skip [N_NODES * HID];
__device__ float g_esrc [N_NODES];
__device__ float g_edst [N_NODES];
__device__ float g_z    [N_NODES];
__device__ float g_p    [N_TOT];
__device__ float g_psum [N_GRAPHS * HID];
__device__ float g_pmax [N_GRAPHS * HID];
__device__ float g_cnt  [N_GRAPHS];

// ---------------- helpers ----------------------------------------------------
__device__ __forceinline__ void atomicMaxF(float* a, float v) {
    if (v >= 0.f) atomicMax((int*)a, __float_as_int(v));
    else          atomicMin((unsigned int*)a, __float_as_uint(v));
}

__device__ __forceinline__ void redAddV4(float* dst, float a, float b, float c, float d) {
    asm volatile("red.global.add.v4.f32 [%0], {%1,%2,%3,%4};"
                 :: "l"(dst), "f"(a), "f"(b), "f"(c), "f"(d) : "memory");
}

// ---------------- GEMM: H = X @ W (+bias), optional e_src/e_dst epilogue -----
// block = 256 threads, 32 rows per block; each thread owns 4 rows x 4 cols.
__global__ void __launch_bounds__(256) gemm128(
    const float* __restrict__ X, const float* __restrict__ W,
    const float* __restrict__ bias,
    const float* __restrict__ a_s, const float* __restrict__ a_d,
    float* __restrict__ H, float* __restrict__ es, float* __restrict__ ed,
    int n, int computeE)
{
    __shared__ float sW[64 * 128];  // 32 KB K-chunk of W
    __shared__ float sX[32 * 64];   // 8 KB row tile of X

    const int tid  = threadIdx.x;
    const int warp = tid >> 5;
    const int lane = tid & 31;
    const int row0 = blockIdx.x * 32;

    float4 acc[4];
#pragma unroll
    for (int r = 0; r < 4; r++) acc[r] = make_float4(0.f, 0.f, 0.f, 0.f);

    for (int k0 = 0; k0 < 128; k0 += 64) {
        // stage W chunk (64x128)
#pragma unroll
        for (int i = 0; i < 8; i++) {
            int idx = tid + i * 256;                     // float4 idx 0..2047
            ((float4*)sW)[idx] = ((const float4*)(W + k0 * 128))[idx];
        }
        // stage X tile (32x64)
#pragma unroll
        for (int i = 0; i < 2; i++) {
            int idx = tid + i * 256;                     // float4 idx 0..511
            int r   = idx >> 4;                          // 16 float4 per row
            int c4  = idx & 15;
            int row = row0 + r;
            float4 v = make_float4(0.f, 0.f, 0.f, 0.f);
            if (row < n) v = ((const float4*)(X + row * 128 + k0))[c4];
            ((float4*)sX)[idx] = v;
        }
        __syncthreads();

        const float* xbase = sX + (warp * 4) * 64;
#pragma unroll
        for (int k4 = 0; k4 < 16; k4++) {
            float4 xr[4];
#pragma unroll
            for (int r = 0; r < 4; r++)
                xr[r] = *(const float4*)(xbase + r * 64 + k4 * 4);
#pragma unroll
            for (int kk = 0; kk < 4; kk++) {
                float4 w4 = *(const float4*)(sW + (k4 * 4 + kk) * 128 + lane * 4);
#pragma unroll
                for (int r = 0; r < 4; r++) {
                    float xv = (kk == 0) ? xr[r].x : (kk == 1) ? xr[r].y
                             : (kk == 2) ? xr[r].z : xr[r].w;
                    acc[r].x += xv * w4.x;
                    acc[r].y += xv * w4.y;
                    acc[r].z += xv * w4.z;
                    acc[r].w += xv * w4.w;
                }
            }
        }
        __syncthreads();
    }

    float4 bv = make_float4(0.f, 0.f, 0.f, 0.f);
    if (bias) bv = *(const float4*)(bias + lane * 4);
    float4 as4 = make_float4(0.f, 0.f, 0.f, 0.f);
    float4 ad4 = make_float4(0.f, 0.f, 0.f, 0.f);
    if (computeE) {
        as4 = *(const float4*)(a_s + lane * 4);
        ad4 = *(const float4*)(a_d + lane * 4);
    }

#pragma unroll
    for (int r = 0; r < 4; r++) {
        int row = row0 + warp * 4 + r;
        if (row < n) {
            float4 h = acc[r];
            h.x += bv.x; h.y += bv.y; h.z += bv.z; h.w += bv.w;
            *(float4*)(H + row * 128 + lane * 4) = h;
            if (computeE) {
                float ps = h.x * as4.x + h.y * as4.y + h.z * as4.z + h.w * as4.w;
                float pd = h.x * ad4.x + h.y * ad4.y + h.z * ad4.z + h.w * ad4.w;
#pragma unroll
                for (int o = 16; o > 0; o >>= 1) {
                    ps += __shfl_xor_sync(0xffffffff, ps, o);
                    pd += __shfl_xor_sync(0xffffffff, pd, o);
                }
                if (lane == 0) { es[row] = ps; ed[row] = pd; }
            }
        }
    }
}

// ---------------- per-layer scratch init -------------------------------------
__global__ void layer_init() {
    int i = blockIdx.x * blockDim.x + threadIdx.x;
    const int tot4 = N_NODES * HID / 4;
    if (i < tot4) ((float4*)g_agg)[i] = make_float4(0.f, 0.f, 0.f, 0.f);
    if (i < N_NODES) g_z[i] = 0.f;
}

// ---------------- softmax numerator + denominator (one pass, no max) ---------
__global__ void edge_softmax_num(const int* __restrict__ ei) {
    int e = blockIdx.x * blockDim.x + threadIdx.x;
    if (e >= N_TOT) return;
    int s, d;
    if (e < N_EDGES) { s = __ldg(ei + e); d = __ldg(ei + N_EDGES + e); }
    else             { s = d = e - N_EDGES; }
    float v = g_esrc[s] + g_edst[d];
    v = fmaxf(v, 0.2f * v);           // leaky_relu, both signs
    float p = expf(v);                // softmax is shift-invariant; logits are O(10)
    g_p[e] = p;
    atomicAdd(&g_z[d], p);
}

// ---------------- weighted scatter: agg[dst] += h[src] * alpha (warp/edge) ---
__global__ void __launch_bounds__(256) edge_aggregate(const int* __restrict__ ei) {
    int w = (blockIdx.x * blockDim.x + threadIdx.x) >> 5;
    int lane = threadIdx.x & 31;
    if (w >= N_TOT) return;
    int s, d;
    if (w < N_EDGES) { s = __ldg(ei + w); d = __ldg(ei + N_EDGES + w); }
    else             { s = d = w - N_EDGES; }
    float alpha = g_p[w] / g_z[d];
    float4 h = *(const float4*)(g_hfeat + s * 128 + lane * 4);
    redAddV4(g_agg + d * 128 + lane * 4,
             h.x * alpha, h.y * alpha, h.z * alpha, h.w * alpha);
}

// ---------------- bias + layernorm + elu + skip (warp per node) --------------
__global__ void __launch_bounds__(256) node_post(
    const float* __restrict__ gat_b, const float* __restrict__ ln_g,
    const float* __restrict__ ln_b, int layer)
{
    int w = (blockIdx.x * blockDim.x + threadIdx.x) >> 5;
    int lane = threadIdx.x & 31;
    if (w >= N_NODES) return;

    float4 v  = *(const float4*)(g_agg + w * 128 + lane * 4);
    float4 b4 = *(const float4*)(gat_b + lane * 4);
    v.x += b4.x; v.y += b4.y; v.z += b4.z; v.w += b4.w;

    float s  = v.x + v.y + v.z + v.w;
    float sq = v.x * v.x + v.y * v.y + v.z * v.z + v.w * v.w;
#pragma unroll
    for (int o = 16; o > 0; o >>= 1) {
        s  += __shfl_xor_sync(0xffffffff, s,  o);
        sq += __shfl_xor_sync(0xffffffff, sq, o);
    }
    float mean = s * (1.f / 128.f);
    float var  = sq * (1.f / 128.f) - mean * mean;
    float rstd = rsqrtf(var + LN_EPS);

    float4 g4 = *(const float4*)(ln_g + lane * 4);
    float4 l4 = *(const float4*)(ln_b + lane * 4);
    float y0 = (v.x - mean) * rstd * g4.x + l4.x;
    float y1 = (v.y - mean) * rstd * g4.y + l4.y;
    float y2 = (v.z - mean) * rstd * g4.z + l4.z;
    float y3 = (v.w - mean) * rstd * g4.w + l4.w;

    if (layer < 3) {   // ELU on all but last layer
        y0 = y0 > 0.f ? y0 : expm1f(y0);
        y1 = y1 > 0.f ? y1 : expm1f(y1);
        y2 = y2 > 0.f ? y2 : expm1f(y2);
        y3 = y3 > 0.f ? y3 : expm1f(y3);
    }

    const float* skp = (layer == 0) ? g_skip : g_hcur;
    float4 sk = *(const float4*)(skp + w * 128 + lane * 4);
    y0 += sk.x; y1 += sk.y; y2 += sk.z; y3 += sk.w;

    *(float4*)(g_hcur + w * 128 + lane * 4) = make_float4(y0, y1, y2, y3);
}

// ---------------- pooling ----------------------------------------------------
__global__ void pool_init() {
    int i = blockIdx.x * blockDim.x + threadIdx.x;
    if (i < N_GRAPHS * HID) {
        g_psum[i] = 0.f;
        g_pmax[i] = __int_as_float(0xFF800000);  // -inf
    }
    if (i < N_GRAPHS) g_cnt[i] = 0.f;
}

__global__ void __launch_bounds__(256) pool_scatter(const int* __restrict__ batch) {
    int w = (blockIdx.x * blockDim.x + threadIdx.x) >> 5;
    int lane = threadIdx.x & 31;
    if (w >= N_NODES) return;
    int g = __ldg(batch + w);
    float4 v = *(const float4*)(g_hcur + w * 128 + lane * 4);
    redAddV4(g_psum + g * 128 + lane * 4, v.x, v.y, v.z, v.w);
    float* pm = g_pmax + g * 128 + lane * 4;
    atomicMaxF(pm + 0, v.x);
    atomicMaxF(pm + 1, v.y);
    atomicMaxF(pm + 2, v.z);
    atomicMaxF(pm + 3, v.w);
    if (lane == 0) atomicAdd(&g_cnt[g], 1.f);
}

// ---------------- MLP head (one block per graph) ------------------------------
__global__ void __launch_bounds__(128) mlp_head(
    const float* __restrict__ W1, const float* __restrict__ b1,
    const float* __restrict__ W2, const float* __restrict__ b2,
    const float* __restrict__ W3, const float* __restrict__ b3,
    float* __restrict__ out)
{
    __shared__ float gv[256];
    __shared__ float h1[128];
    __shared__ float h2[64];
    int g = blockIdx.x, t = threadIdx.x;

    float cnt = fmaxf(g_cnt[g], 1.f);
    gv[t]       = g_psum[g * 128 + t] / cnt;  // mean half
    gv[128 + t] = g_pmax[g * 128 + t];        // max half
    __syncthreads();

    float a1 = b1[t];
#pragma unroll 8
    for (int k = 0; k < 256; k++) a1 += gv[k] * W1[k * 128 + t];
    h1[t] = fmaxf(a1, 0.f);
    __syncthreads();

    if (t < 64) {
        float a2 = b2[t];
#pragma unroll 8
        for (int k = 0; k < 128; k++) a2 += h1[k] * W2[k * 64 + t];
        h2[t] = fmaxf(a2, 0.f);
    }
    __syncthreads();

    if (t < 4) {
        float a3 = b3[t];
#pragma unroll
        for (int k = 0; k < 64; k++) a3 += h2[k] * W3[k * 4 + t];
        out[g * 4 + t] = a3;
    }
}

// ---------------- launch ------------------------------------------------------
extern "C" void kernel_launch(void* const* d_in, const int* in_sizes, int n_in,
                              void* d_out, int out_size)
{
    const float* x      = (const float*)d_in[0];
    const int*   ei     = (const int*)  d_in[1];
    const int*   batch  = (const int*)  d_in[2];
    const float* Ws     = (const float*)d_in[3];
    const float* a_src  = (const float*)d_in[4];
    const float* a_dst  = (const float*)d_in[5];
    const float* gat_b  = (const float*)d_in[6];
    const float* ln_g   = (const float*)d_in[7];
    const float* ln_b   = (const float*)d_in[8];
    const float* skip_W = (const float*)d_in[9];
    const float* skip_b = (const float*)d_in[10];
    const float* W1 = (const float*)d_in[11];
    const float* b1 = (const float*)d_in[12];
    const float* W2 = (const float*)d_in[13];
    const float* b2 = (const float*)d_in[14];
    const float* W3 = (const float*)d_in[15];
    const float* b3 = (const float*)d_in[16];

    float *hcur, *hfeat, *skip, *esrc, *edst;
    cudaGetSymbolAddress((void**)&hcur,  g_hcur);
    cudaGetSymbolAddress((void**)&hfeat, g_hfeat);
    cudaGetSymbolAddress((void**)&skip,  g_skip);
    cudaGetSymbolAddress((void**)&esrc,  g_esrc);
    cudaGetSymbolAddress((void**)&edst,  g_edst);

    const int gemm_blocks = (N_NODES + 31) / 32;
    const int init_blocks = (N_NODES * HID / 4 + 255) / 256;
    const int edge_blocks = (N_TOT + 255) / 256;
    const int eagg_blocks = (int)(((long long)N_TOT * 32 + 255) / 256);
    const int node_blocks = (N_NODES * 32 + 255) / 256;

    // skip projection: skip = x @ skip_W + skip_b
    gemm128<<<gemm_blocks, 256>>>(x, skip_W, skip_b, nullptr, nullptr,
                                  skip, nullptr, nullptr, N_NODES, 0);

    for (int l = 0; l < 4; l++) {
        const float* in = (l == 0) ? x : hcur;
        gemm128<<<gemm_blocks, 256>>>(in, Ws + l * 128 * 128, nullptr,
                                      a_src + l * 128, a_dst + l * 128,
                                      hfeat, esrc, edst, N_NODES, 1);
        layer_init<<<init_blocks, 256>>>();
        edge_softmax_num<<<edge_blocks, 256>>>(ei);
        edge_aggregate<<<eagg_blocks, 256>>>(ei);
        node_post<<<node_blocks, 256>>>(gat_b + l * 128, ln_g + l * 128,
                                        ln_b + l * 128, l);
    }

    pool_init<<<(N_GRAPHS * HID + 255) / 256, 256>>>();
    pool_scatter<<<node_blocks, 256>>>(batch);
    mlp_head<<<N_GRAPHS, 128>>>(W1, b1, W2, b2, W3, b3, (float*)d_out);
}

// round 2
// speedup vs baseline: 1.3277x; 1.3277x over previous
#include <cuda_runtime.h>
#include <math.h>

#define N_NODES 50000
#define N_EDGES 800000
#define HID     128
#define N_GRAPHS 32
#define LN_EPS  1e-5f
#define SCAN_BLK ((N_NODES + 1023) / 1024)   // 49

// ---------------- scratch (device globals; no allocation allowed) ------------
__device__ float g_hcur [N_NODES * HID];
__device__ float g_hfeat[N_NODES * HID];
__device__ float g_agg  [N_NODES * HID];
__device__ float g_skip [N_NODES * HID];
__device__ float g_esrc [N_NODES];
__device__ float g_edst [N_NODES];
__device__ float g_psum [N_GRAPHS * HID];
__device__ float g_pmax [N_GRAPHS * HID];
__device__ float g_cnt  [N_GRAPHS];
// CSR scratch
__device__ int   g_deg     [N_NODES];
__device__ int   g_rowstart[N_NODES + 1];
__device__ int   g_cursor  [N_NODES];
__device__ int   g_blksum  [SCAN_BLK];
__device__ int   g_blkoff  [SCAN_BLK];
__device__ int   g_csr_src [N_EDGES];

// ---------------- helpers ----------------------------------------------------
__device__ __forceinline__ void atomicMaxF(float* a, float v) {
    if (v >= 0.f) atomicMax((int*)a, __float_as_int(v));
    else          atomicMin((unsigned int*)a, __float_as_uint(v));
}

__device__ __forceinline__ void redAddV4(float* dst, float a, float b, float c, float d) {
    asm volatile("red.global.add.v4.f32 [%0], {%1,%2,%3,%4};"
                 :: "l"(dst), "f"(a), "f"(b), "f"(c), "f"(d) : "memory");
}

// =============================================================================
// GEMM: H = X @ W (+bias), optional e_src/e_dst epilogue
// BM=64 rows, BN=128, BK=32. 256 threads. Each thread: 8 rows x 4 cols.
// =============================================================================
__global__ void __launch_bounds__(256) gemm128(
    const float* __restrict__ X, const float* __restrict__ W,
    const float* __restrict__ bias,
    const float* __restrict__ a_s, const float* __restrict__ a_d,
    float* __restrict__ H, float* __restrict__ es, float* __restrict__ ed,
    int n, int computeE)
{
    __shared__ float sW [32 * 128];   // 16 KB  (K-chunk of W, row-major)
    __shared__ float sXT[32 * 64];    //  8 KB  (X tile, transposed: [k][row])

    const int tid  = threadIdx.x;
    const int warp = tid >> 5;
    const int lane = tid & 31;
    const int row0 = blockIdx.x * 64;

    float4 acc[8];
#pragma unroll
    for (int r = 0; r < 8; r++) acc[r] = make_float4(0.f, 0.f, 0.f, 0.f);

    for (int k0 = 0; k0 < 128; k0 += 32) {
        // stage W chunk (32 x 128)
#pragma unroll
        for (int i = 0; i < 4; i++) {
            int idx = tid + i * 256;                     // float4 idx 0..1023
            ((float4*)sW)[idx] = ((const float4*)(W + k0 * 128))[idx];
        }
        // stage X tile transposed (rows 64 x k 32)
#pragma unroll
        for (int i = 0; i < 2; i++) {
            int t   = tid + i * 256;                     // 0..511
            int row = t & 63;
            int c4  = t >> 6;                            // k-group (0..7)
            int grow = row0 + row;
            float4 v = make_float4(0.f, 0.f, 0.f, 0.f);
            if (grow < n) v = ((const float4*)(X + grow * 128 + k0))[c4];
            sXT[(c4 * 4 + 0) * 64 + row] = v.x;
            sXT[(c4 * 4 + 1) * 64 + row] = v.y;
            sXT[(c4 * 4 + 2) * 64 + row] = v.z;
            sXT[(c4 * 4 + 3) * 64 + row] = v.w;
        }
        __syncthreads();

#pragma unroll
        for (int k = 0; k < 32; k++) {
            float4 w4 = *(const float4*)(sW  + k * 128 + lane * 4);
            float4 xa = *(const float4*)(sXT + k * 64  + warp * 8);
            float4 xb = *(const float4*)(sXT + k * 64  + warp * 8 + 4);
            float xv[8] = {xa.x, xa.y, xa.z, xa.w, xb.x, xb.y, xb.z, xb.w};
#pragma unroll
            for (int r = 0; r < 8; r++) {
                acc[r].x += xv[r] * w4.x;
                acc[r].y += xv[r] * w4.y;
                acc[r].z += xv[r] * w4.z;
                acc[r].w += xv[r] * w4.w;
            }
        }
        __syncthreads();
    }

    float4 bv = make_float4(0.f, 0.f, 0.f, 0.f);
    if (bias) bv = *(const float4*)(bias + lane * 4);
    float4 as4 = make_float4(0.f, 0.f, 0.f, 0.f);
    float4 ad4 = make_float4(0.f, 0.f, 0.f, 0.f);
    if (computeE) {
        as4 = *(const float4*)(a_s + lane * 4);
        ad4 = *(const float4*)(a_d + lane * 4);
    }

#pragma unroll
    for (int r = 0; r < 8; r++) {
        int row = row0 + warp * 8 + r;
        if (row < n) {
            float4 h = acc[r];
            h.x += bv.x; h.y += bv.y; h.z += bv.z; h.w += bv.w;
            *(float4*)(H + row * 128 + lane * 4) = h;
            if (computeE) {
                float ps = h.x * as4.x + h.y * as4.y + h.z * as4.z + h.w * as4.w;
                float pd = h.x * ad4.x + h.y * ad4.y + h.z * ad4.z + h.w * ad4.w;
#pragma unroll
                for (int o = 16; o > 0; o >>= 1) {
                    ps += __shfl_xor_sync(0xffffffff, ps, o);
                    pd += __shfl_xor_sync(0xffffffff, pd, o);
                }
                if (lane == 0) { es[row] = ps; ed[row] = pd; }
            }
        }
    }
}

// =============================================================================
// CSR construction (by destination)
// =============================================================================
__global__ void csr_zero() {
    int i = blockIdx.x * blockDim.x + threadIdx.x;
    if (i < N_NODES) g_deg[i] = 0;
}

__global__ void csr_hist(const int* __restrict__ ei) {
    int e = blockIdx.x * blockDim.x + threadIdx.x;
    if (e < N_EDGES) atomicAdd(&g_deg[__ldg(ei + N_EDGES + e)], 1);
}

__global__ void __launch_bounds__(1024) csr_scan1() {
    __shared__ int sh[1024];
    int i = blockIdx.x * 1024 + threadIdx.x;
    int v = (i < N_NODES) ? g_deg[i] : 0;
    sh[threadIdx.x] = v;
    __syncthreads();
#pragma unroll
    for (int off = 1; off < 1024; off <<= 1) {
        int t = (threadIdx.x >= off) ? sh[threadIdx.x - off] : 0;
        __syncthreads();
        sh[threadIdx.x] += t;
        __syncthreads();
    }
    if (i < N_NODES) g_rowstart[i] = sh[threadIdx.x] - v;   // exclusive
    if (threadIdx.x == 1023) g_blksum[blockIdx.x] = sh[1023];
}

__global__ void __launch_bounds__(64) csr_scan2() {
    __shared__ int sh[64];
    int t = threadIdx.x;
    int v = (t < SCAN_BLK) ? g_blksum[t] : 0;
    sh[t] = v;
    __syncthreads();
#pragma unroll
    for (int off = 1; off < 64; off <<= 1) {
        int u = (t >= off) ? sh[t - off] : 0;
        __syncthreads();
        sh[t] += u;
        __syncthreads();
    }
    if (t < SCAN_BLK) g_blkoff[t] = sh[t] - v;              // exclusive
}

__global__ void csr_scan3() {
    int i = blockIdx.x * blockDim.x + threadIdx.x;
    if (i < N_NODES) {
        int r = g_rowstart[i] + g_blkoff[i >> 10];
        g_rowstart[i] = r;
        g_cursor[i]   = r;
    }
    if (i == 0) g_rowstart[N_NODES] = N_EDGES;
}

__global__ void csr_scatter(const int* __restrict__ ei) {
    int e = blockIdx.x * blockDim.x + threadIdx.x;
    if (e >= N_EDGES) return;
    int s = __ldg(ei + e);
    int d = __ldg(ei + N_EDGES + e);
    int pos = atomicAdd(&g_cursor[d], 1);
    g_csr_src[pos] = s;
}

// =============================================================================
// Fused edge phase: softmax (no-max; logits are O(1)) + weighted gather.
// One warp per destination node. Zero atomics, zero intermediate arrays.
// =============================================================================
__device__ __forceinline__ float edge_p(float esrc, float edst) {
    float v = esrc + edst;
    v = fmaxf(v, 0.2f * v);          // leaky_relu
    return __expf(v);
}

__global__ void __launch_bounds__(256) edge_gather() {
    int w = (blockIdx.x * blockDim.x + threadIdx.x) >> 5;
    int lane = threadIdx.x & 31;
    if (w >= N_NODES) return;

    float ed = __ldg(g_edst + w);

    // self loop
    float p = edge_p(__ldg(g_esrc + w), ed);
    float z = p;
    float4 hv = *(const float4*)(g_hfeat + (long)w * 128 + lane * 4);
    float4 acc = make_float4(p * hv.x, p * hv.y, p * hv.z, p * hv.w);

    int i   = g_rowstart[w];
    int end = g_rowstart[w + 1];

    for (; i + 2 <= end; i += 2) {
        int s0 = __ldg(g_csr_src + i);
        int s1 = __ldg(g_csr_src + i + 1);
        float p0 = edge_p(__ldg(g_esrc + s0), ed);
        float p1 = edge_p(__ldg(g_esrc + s1), ed);
        float4 h0 = *(const float4*)(g_hfeat + (long)s0 * 128 + lane * 4);
        float4 h1 = *(const float4*)(g_hfeat + (long)s1 * 128 + lane * 4);
        z += p0 + p1;
        acc.x += p0 * h0.x + p1 * h1.x;
        acc.y += p0 * h0.y + p1 * h1.y;
        acc.z += p0 * h0.z + p1 * h1.z;
        acc.w += p0 * h0.w + p1 * h1.w;
    }
    if (i < end) {
        int s0 = __ldg(g_csr_src + i);
        float p0 = edge_p(__ldg(g_esrc + s0), ed);
        float4 h0 = *(const float4*)(g_hfeat + (long)s0 * 128 + lane * 4);
        z += p0;
        acc.x += p0 * h0.x; acc.y += p0 * h0.y;
        acc.z += p0 * h0.z; acc.w += p0 * h0.w;
    }

    float inv = __fdividef(1.f, z);
    acc.x *= inv; acc.y *= inv; acc.z *= inv; acc.w *= inv;
    *(float4*)(g_agg + (long)w * 128 + lane * 4) = acc;
}

// =============================================================================
// bias + layernorm + elu + skip (warp per node); layer 3 fuses pooling
// =============================================================================
__global__ void __launch_bounds__(256) node_post(
    const float* __restrict__ gat_b, const float* __restrict__ ln_g,
    const float* __restrict__ ln_b, const int* __restrict__ batch, int layer)
{
    int w = (blockIdx.x * blockDim.x + threadIdx.x) >> 5;
    int lane = threadIdx.x & 31;
    if (w >= N_NODES) return;

    float4 v  = *(const float4*)(g_agg + (long)w * 128 + lane * 4);
    float4 b4 = *(const float4*)(gat_b + lane * 4);
    v.x += b4.x; v.y += b4.y; v.z += b4.z; v.w += b4.w;

    float s  = v.x + v.y + v.z + v.w;
    float sq = v.x * v.x + v.y * v.y + v.z * v.z + v.w * v.w;
#pragma unroll
    for (int o = 16; o > 0; o >>= 1) {
        s  += __shfl_xor_sync(0xffffffff, s,  o);
        sq += __shfl_xor_sync(0xffffffff, sq, o);
    }
    float mean = s * (1.f / 128.f);
    float var  = sq * (1.f / 128.f) - mean * mean;
    float rstd = rsqrtf(var + LN_EPS);

    float4 g4 = *(const float4*)(ln_g + lane * 4);
    float4 l4 = *(const float4*)(ln_b + lane * 4);
    float y0 = (v.x - mean) * rstd * g4.x + l4.x;
    float y1 = (v.y - mean) * rstd * g4.y + l4.y;
    float y2 = (v.z - mean) * rstd * g4.z + l4.z;
    float y3 = (v.w - mean) * rstd * g4.w + l4.w;

    if (layer < 3) {   // ELU on all but last layer
        y0 = y0 > 0.f ? y0 : expm1f(y0);
        y1 = y1 > 0.f ? y1 : expm1f(y1);
        y2 = y2 > 0.f ? y2 : expm1f(y2);
        y3 = y3 > 0.f ? y3 : expm1f(y3);
    }

    const float* skp = (layer == 0) ? g_skip : g_hcur;
    float4 sk = *(const float4*)(skp + (long)w * 128 + lane * 4);
    y0 += sk.x; y1 += sk.y; y2 += sk.z; y3 += sk.w;

    *(float4*)(g_hcur + (long)w * 128 + lane * 4) = make_float4(y0, y1, y2, y3);

    if (layer == 3) {   // fused global pooling
        int g = __ldg(batch + w);
        redAddV4(g_psum + g * 128 + lane * 4, y0, y1, y2, y3);
        float* pm = g_pmax + g * 128 + lane * 4;
        atomicMaxF(pm + 0, y0);
        atomicMaxF(pm + 1, y1);
        atomicMaxF(pm + 2, y2);
        atomicMaxF(pm + 3, y3);
        if (lane == 0) atomicAdd(&g_cnt[g], 1.f);
    }
}

// ---------------- pooling init ------------------------------------------------
__global__ void pool_init() {
    int i = blockIdx.x * blockDim.x + threadIdx.x;
    if (i < N_GRAPHS * HID) {
        g_psum[i] = 0.f;
        g_pmax[i] = __int_as_float(0xFF800000);  // -inf
    }
    if (i < N_GRAPHS) g_cnt[i] = 0.f;
}

// ---------------- MLP head (one block per graph) ------------------------------
__global__ void __launch_bounds__(128) mlp_head(
    const float* __restrict__ W1, const float* __restrict__ b1,
    const float* __restrict__ W2, const float* __restrict__ b2,
    const float* __restrict__ W3, const float* __restrict__ b3,
    float* __restrict__ out)
{
    __shared__ float gv[256];
    __shared__ float h1[128];
    __shared__ float h2[64];
    int g = blockIdx.x, t = threadIdx.x;

    float cnt = fmaxf(g_cnt[g], 1.f);
    gv[t]       = g_psum[g * 128 + t] / cnt;  // mean half
    gv[128 + t] = g_pmax[g * 128 + t];        // max half
    __syncthreads();

    float a1 = b1[t];
#pragma unroll 8
    for (int k = 0; k < 256; k++) a1 += gv[k] * W1[k * 128 + t];
    h1[t] = fmaxf(a1, 0.f);
    __syncthreads();

    if (t < 64) {
        float a2 = b2[t];
#pragma unroll 8
        for (int k = 0; k < 128; k++) a2 += h1[k] * W2[k * 64 + t];
        h2[t] = fmaxf(a2, 0.f);
    }
    __syncthreads();

    if (t < 4) {
        float a3 = b3[t];
#pragma unroll
        for (int k = 0; k < 64; k++) a3 += h2[k] * W3[k * 4 + t];
        out[g * 4 + t] = a3;
    }
}

// ---------------- launch ------------------------------------------------------
extern "C" void kernel_launch(void* const* d_in, const int* in_sizes, int n_in,
                              void* d_out, int out_size)
{
    const float* x      = (const float*)d_in[0];
    const int*   ei     = (const int*)  d_in[1];
    const int*   batch  = (const int*)  d_in[2];
    const float* Ws     = (const float*)d_in[3];
    const float* a_src  = (const float*)d_in[4];
    const float* a_dst  = (const float*)d_in[5];
    const float* gat_b  = (const float*)d_in[6];
    const float* ln_g   = (const float*)d_in[7];
    const float* ln_b   = (const float*)d_in[8];
    const float* skip_W = (const float*)d_in[9];
    const float* skip_b = (const float*)d_in[10];
    const float* W1 = (const float*)d_in[11];
    const float* b1 = (const float*)d_in[12];
    const float* W2 = (const float*)d_in[13];
    const float* b2 = (const float*)d_in[14];
    const float* W3 = (const float*)d_in[15];
    const float* b3 = (const float*)d_in[16];

    float *hcur, *hfeat, *skip, *esrc, *edst;
    cudaGetSymbolAddress((void**)&hcur,  g_hcur);
    cudaGetSymbolAddress((void**)&hfeat, g_hfeat);
    cudaGetSymbolAddress((void**)&skip,  g_skip);
    cudaGetSymbolAddress((void**)&esrc,  g_esrc);
    cudaGetSymbolAddress((void**)&edst,  g_edst);

    const int gemm_blocks = (N_NODES + 63) / 64;
    const int node_blocks = (N_NODES * 32 + 255) / 256;   // warp per node
    const int edge_blocks = (N_EDGES + 255) / 256;
    const int nn_blocks   = (N_NODES + 255) / 256;

    // CSR build (dst-major)
    csr_zero   <<<nn_blocks, 256>>>();
    csr_hist   <<<edge_blocks, 256>>>(ei);
    csr_scan1  <<<SCAN_BLK, 1024>>>();
    csr_scan2  <<<1, 64>>>();
    csr_scan3  <<<nn_blocks, 256>>>();
    csr_scatter<<<edge_blocks, 256>>>(ei);

    pool_init<<<(N_GRAPHS * HID + 255) / 256, 256>>>();

    // skip projection
    gemm128<<<gemm_blocks, 256>>>(x, skip_W, skip_b, nullptr, nullptr,
                                  skip, nullptr, nullptr, N_NODES, 0);

    for (int l = 0; l < 4; l++) {
        const float* in = (l == 0) ? x : hcur;
        gemm128<<<gemm_blocks, 256>>>(in, Ws + l * 128 * 128, nullptr,
                                      a_src + l * 128, a_dst + l * 128,
                                      hfeat, esrc, edst, N_NODES, 1);
        edge_gather<<<node_blocks, 256>>>();
        node_post<<<node_blocks, 256>>>(gat_b + l * 128, ln_g + l * 128,
                                        ln_b + l * 128, batch, l);
    }

    mlp_head<<<N_GRAPHS, 128>>>(W1, b1, W2, b2, W3, b3, (float*)d_out);
}